// round 8
// baseline (speedup 1.0000x reference)
#include <cuda_runtime.h>

#define NND 100000
#define NE  1000000

// ---------------- device scratch (static, allocation-free) ----------------
__device__ float g_agg1[(size_t)NND * 64];   // layer-1 neighbor sum of x
__device__ float g_agg2[(size_t)NND * 64];   // layer-2 neighbor sum of p
__device__ float g_h   [(size_t)NND * 128];  // hidden activations
__device__ float g_p   [(size_t)NND * 64];   // h @ W2l (pre-aggregation)
__device__ float g_rinv[NND];                // 1 / max(cnt,1)
__device__ int   g_cnt [NND];
__device__ int   g_src [NE];
__device__ int   g_dst [NE];

// ---------------- f32x2 helpers (sm_103a packed fp32 SIMD) ----------------
__device__ __forceinline__ unsigned long long pk2(float lo, float hi) {
    unsigned long long r;
    asm("mov.b64 %0, {%1, %2};" : "=l"(r) : "f"(lo), "f"(hi));
    return r;
}
__device__ __forceinline__ void upk2(float& lo, float& hi, unsigned long long v) {
    asm("mov.b64 {%0, %1}, %2;" : "=f"(lo), "=f"(hi) : "l"(v));
}
#define FMA2(d, a, b) \
    asm("fma.rn.f32x2 %0, %1, %2, %0;" : "+l"(d) : "l"(a), "l"(b))

// ---------------- init: zero accumulators, copy+clamp int32 edges ----------------
__global__ void k_init(const int* __restrict__ ei) {
    int i = blockIdx.x * 256 + threadIdx.x;          // exactly NND*64 = 6.4M threads
    g_agg1[i] = 0.f;
    g_agg2[i] = 0.f;
    if (i < NND) g_cnt[i] = 0;
    if (i < NE) {
        int s = ei[i];
        int d = ei[NE + i];
        g_src[i] = (s < 0) ? 0 : (s >= NND ? NND - 1 : s);
        g_dst[i] = (d < 0) ? 0 : (d >= NND ? NND - 1 : d);
    }
}

// ---------------- scatter: agg[dst] += feat[src] (64 floats/edge) ----------------
template <int LAYER>
__global__ void k_scatter(const float* __restrict__ xin) {
    int t = blockIdx.x * 256 + threadIdx.x;          // exactly NE*16 = 16M threads
    int e = t >> 4;
    int c = t & 15;
    int s = g_src[e];
    int d = g_dst[e];
    const float* feat = (LAYER == 1) ? xin : g_p;
    float*       agg  = (LAYER == 1) ? g_agg1 : g_agg2;
    float4 v = __ldg((const float4*)feat + (size_t)s * 16 + c);
    float* a = agg + (size_t)d * 64 + (c << 2);
    asm volatile("red.global.add.v4.f32 [%0], {%1,%2,%3,%4};"
                 :: "l"(a), "f"(v.x), "f"(v.y), "f"(v.z), "f"(v.w) : "memory");
    if (LAYER == 1 && c == 0) atomicAdd(&g_cnt[d], 1);
}

// ---------------- unified 128x128x128 GEMM, f32x2, mov-free inner loop ----------------
// Tile: 128 nodes x 128 cols. K staged in 4 chunks of 32.
// A stored DUPLICATED in smem ((a,a) ull pairs) -> LDS.64 is a ready f32x2 operand.
// W loaded as ulonglong2 -> (w[c],w[c+1]) pairs ready, no packing movs.
// MODE 1: h = relu( concat(agg1*rinv, x) @ [W1l;W1r] + b1 )  (chunks 0-1 = mean, 2-3 = x)
// MODE 2: cols 0-63 -> g_p = h @ W2l ; cols 64-127 -> out = h @ W2r + b2
// 256 threads, bits: cglo=tid[0:2) nglo=tid[2:4) cghi=tid[4:6) nghi=tid[6:8).
// cg = cglo+4*cghi (8 cols), ng = nglo+4*nghi (nodes ng+16j). 32 f32x2 accs.
extern __shared__ float sm[];

#define A_STRIDE 33   // ulls per node row (32 k-pairs + 1 pad)

template <int MODE>
__global__ __launch_bounds__(256, 2)
void k_gemm(const float* __restrict__ xin, const float* __restrict__ Wa,
            const float* __restrict__ Wb, const float* __restrict__ bias,
            float* __restrict__ outr) {
    float* Ws = sm;                                      // 128 k x 128 c floats
    unsigned long long* As2 = (unsigned long long*)(sm + 16384);  // 128 x A_STRIDE ulls
    int tid = threadIdx.x;
    int nodeB = blockIdx.x * 128;

    // ---- stage W fully (4096 float4) ----
    #pragma unroll
    for (int m = 0; m < 16; m++) {
        int j = tid + 256 * m;
        int k = j >> 5, c4 = j & 31;
        float4 v;
        if (MODE == 1) {             // stacked rows: 0-63 W1l, 64-127 W1r
            v = __ldg((const float4*)(k < 64 ? Wa : Wb) + (k & 63) * 32 + c4);
        } else {                     // side-by-side: cols 0-63 W2l, 64-127 W2r
            v = (c4 < 16) ? __ldg((const float4*)Wa + k * 16 + c4)
                          : __ldg((const float4*)Wb + k * 16 + (c4 - 16));
        }
        ((float4*)Ws)[j] = v;
    }

    int cglo = tid & 3;
    int nglo = (tid >> 2) & 3;
    int cghi = (tid >> 4) & 3;
    int nghi = tid >> 6;
    int cg = cglo + 4 * cghi;        // 0..15 -> cols cg*8..+7
    int ng = nglo + 4 * nghi;        // 0..15 -> nodes ng+16j

    // ---- bias / acc init ----
    float bv[8];
    #pragma unroll
    for (int q = 0; q < 8; q++) {
        if (MODE == 1)      bv[q] = __ldg(bias + cg * 8 + q);
        else if (cg >= 8)   bv[q] = __ldg(bias + (cg - 8) * 8 + q);
        else                bv[q] = 0.f;
    }
    unsigned long long acc[8][4];
    #pragma unroll
    for (int j = 0; j < 8; j++) {
        acc[j][0] = pk2(bv[0], bv[1]);
        acc[j][1] = pk2(bv[2], bv[3]);
        acc[j][2] = pk2(bv[4], bv[5]);
        acc[j][3] = pk2(bv[6], bv[7]);
    }

    // ---- 4 K-chunks of 32 ----
    for (int c = 0; c < 4; c++) {
        __syncthreads();             // protect As2 from previous chunk's readers
        // stage A chunk duplicated: 1024 source float4 -> 4096 dup ull pairs
        #pragma unroll
        for (int m = 0; m < 4; m++) {
            int i = tid + 256 * m;
            int k4 = i & 7, node = i >> 3;     // k4: 8 float4-groups = 32 k
            int gnode = nodeB + node;
            float4 v = make_float4(0.f, 0.f, 0.f, 0.f);
            if (gnode < NND) {
                if (MODE == 1) {
                    if (c < 2) {     // k 0..63 : mean = agg1 * rinv
                        v = *((const float4*)g_agg1 + (size_t)gnode * 16 + c * 8 + k4);
                        int cn = g_cnt[gnode];
                        float ri = 1.f / (float)(cn < 1 ? 1 : cn);
                        v.x *= ri; v.y *= ri; v.z *= ri; v.w *= ri;
                        if (c == 0 && k4 == 0) g_rinv[gnode] = ri;
                    } else {         // k 64..127 : x
                        v = __ldg((const float4*)xin + (size_t)gnode * 16 + (c - 2) * 8 + k4);
                    }
                } else {
                    v = *((const float4*)g_h + (size_t)gnode * 32 + c * 8 + k4);
                }
            }
            unsigned long long* ar = As2 + node * A_STRIDE + k4 * 4;
            ar[0] = pk2(v.x, v.x);
            ar[1] = pk2(v.y, v.y);
            ar[2] = pk2(v.z, v.z);
            ar[3] = pk2(v.w, v.w);
        }
        __syncthreads();

        // compute 32 k of this chunk; all FMA2 operands direct from smem
        #pragma unroll 8
        for (int kl = 0; kl < 32; kl++) {
            const ulonglong2* wrow =
                (const ulonglong2*)(Ws + (c * 32 + kl) * 128 + cg * 8);
            ulonglong2 wA = wrow[0];     // cols (0,1),(2,3)
            ulonglong2 wB = wrow[1];     // cols (4,5),(6,7)
            unsigned long long aa[8];
            #pragma unroll
            for (int j = 0; j < 8; j++)
                aa[j] = As2[(ng + 16 * j) * A_STRIDE + kl];
            #pragma unroll
            for (int j = 0; j < 8; j++) {
                FMA2(acc[j][0], aa[j], wA.x);
                FMA2(acc[j][1], aa[j], wA.y);
                FMA2(acc[j][2], aa[j], wB.x);
                FMA2(acc[j][3], aa[j], wB.y);
            }
        }
    }

    // ---- write out ----
    #pragma unroll
    for (int j = 0; j < 8; j++) {
        int node = nodeB + ng + 16 * j;
        if (node < NND) {
            float f0,f1,f2,f3,f4,f5,f6,f7;
            upk2(f0, f1, acc[j][0]);
            upk2(f2, f3, acc[j][1]);
            upk2(f4, f5, acc[j][2]);
            upk2(f6, f7, acc[j][3]);
            if (MODE == 1) {
                float* dp = g_h + (size_t)node * 128 + cg * 8;
                *(float4*)(dp)     = make_float4(fmaxf(f0,0.f), fmaxf(f1,0.f),
                                                 fmaxf(f2,0.f), fmaxf(f3,0.f));
                *(float4*)(dp + 4) = make_float4(fmaxf(f4,0.f), fmaxf(f5,0.f),
                                                 fmaxf(f6,0.f), fmaxf(f7,0.f));
            } else {
                float* dst = (cg < 8) ? (g_p + (size_t)node * 64 + cg * 8)
                                      : (outr + (size_t)node * 64 + (cg - 8) * 8);
                *(float4*)(dst)     = make_float4(f0, f1, f2, f3);
                *(float4*)(dst + 4) = make_float4(f4, f5, f6, f7);
            }
        }
    }
}

// ---------------- finalize: out += agg2 * rinv ----------------
__global__ void k_final(float* __restrict__ out) {
    int t = blockIdx.x * 256 + threadIdx.x;     // exactly NND*16 = 1.6M threads
    int node = t >> 4;
    float ri = g_rinv[node];
    float4 a = ((const float4*)g_agg2)[t];
    float4 o = ((float4*)out)[t];
    o.x = fmaf(a.x, ri, o.x);
    o.y = fmaf(a.y, ri, o.y);
    o.z = fmaf(a.z, ri, o.z);
    o.w = fmaf(a.w, ri, o.w);
    ((float4*)out)[t] = o;
}

// ---------------- launch ----------------
extern "C" void kernel_launch(void* const* d_in, const int* in_sizes, int n_in,
                              void* d_out, int out_size) {
    const float* x   = nullptr;
    const float* b1  = nullptr;
    const float* b2  = nullptr;
    const int*   ei  = nullptr;
    const float* W[4] = {nullptr, nullptr, nullptr, nullptr};
    int wn = 0;
    for (int i = 0; i < n_in; i++) {
        int sz = in_sizes[i];
        if      (sz == NND * 64)  x  = (const float*)d_in[i];
        else if (sz == 2 * NE)    ei = (const int*)d_in[i];
        else if (sz == 128)       b1 = (const float*)d_in[i];
        else if (sz == 64)        b2 = (const float*)d_in[i];
        else if (sz == 8192 && wn < 4) W[wn++] = (const float*)d_in[i];
    }
    const float* W1l = W[0];
    const float* W1r = W[1];
    const float* W2l = W[2];
    const float* W2r = W[3];
    float* out = (float*)d_out;

    const int SMG = 65536 + 128 * A_STRIDE * 8;  // 64KB W + 33.8KB A-dup = 99328+ B
    cudaFuncSetAttribute(k_gemm<1>, cudaFuncAttributeMaxDynamicSharedMemorySize, SMG);
    cudaFuncSetAttribute(k_gemm<2>, cudaFuncAttributeMaxDynamicSharedMemorySize, SMG);

    int gemm_blocks = (NND + 127) / 128;         // 782

    k_init<<<25000, 256>>>(ei);                  // NND*64 threads
    k_scatter<1><<<62500, 256>>>(x);             // NE*16 threads, also counts degrees
    k_gemm<1><<<gemm_blocks, 256, SMG>>>(x, W1l, W1r, b1, nullptr);
    k_gemm<2><<<gemm_blocks, 256, SMG>>>(nullptr, W2l, W2r, b2, out);
    k_scatter<2><<<62500, 256>>>(nullptr);       // p -> agg2
    k_final<<<6250, 256>>>(out);                 // NND*16 threads
}

// round 9
// speedup vs baseline: 1.1494x; 1.1494x over previous
#include <cuda_runtime.h>

#define NND 100000
#define NE  1000000

// ---------------- device scratch (static, allocation-free) ----------------
__device__ float g_agg1[(size_t)NND * 64];   // layer-1 neighbor sum of x
__device__ float g_agg2[(size_t)NND * 64];   // layer-2 neighbor sum of p
__device__ float g_h   [(size_t)NND * 128];  // hidden activations
__device__ float g_p   [(size_t)NND * 64];   // h @ W2l (pre-aggregation)
__device__ float g_rinv[NND];                // 1 / max(cnt,1)
__device__ int   g_cnt [NND];
__device__ int   g_src [NE];
__device__ int   g_dst [NE];

// ---------------- f32x2 helpers (sm_103a packed fp32 SIMD) ----------------
__device__ __forceinline__ unsigned long long pk2(float lo, float hi) {
    unsigned long long r;
    asm("mov.b64 %0, {%1, %2};" : "=l"(r) : "f"(lo), "f"(hi));
    return r;
}
__device__ __forceinline__ void upk2(float& lo, float& hi, unsigned long long v) {
    asm("mov.b64 {%0, %1}, %2;" : "=f"(lo), "=f"(hi) : "l"(v));
}
#define FMA2(d, a, b) \
    asm("fma.rn.f32x2 %0, %1, %2, %0;" : "+l"(d) : "l"(a), "l"(b))

// ---------------- init: zero accumulators, copy+clamp int32 edges ----------------
__global__ void k_init(const int* __restrict__ ei) {
    int i = blockIdx.x * 256 + threadIdx.x;          // exactly NND*64 = 6.4M threads
    g_agg1[i] = 0.f;
    g_agg2[i] = 0.f;
    if (i < NND) g_cnt[i] = 0;
    if (i < NE) {
        int s = ei[i];
        int d = ei[NE + i];
        g_src[i] = (s < 0) ? 0 : (s >= NND ? NND - 1 : s);
        g_dst[i] = (d < 0) ? 0 : (d >= NND ? NND - 1 : d);
    }
}

// ---------------- scatter: agg[dst] += feat[src] (64 floats/edge) ----------------
template <int LAYER>
__global__ void k_scatter(const float* __restrict__ xin) {
    int t = blockIdx.x * 256 + threadIdx.x;          // exactly NE*16 = 16M threads
    int e = t >> 4;
    int c = t & 15;
    int s = g_src[e];
    int d = g_dst[e];
    const float* feat = (LAYER == 1) ? xin : g_p;
    float*       agg  = (LAYER == 1) ? g_agg1 : g_agg2;
    float4 v = __ldg((const float4*)feat + (size_t)s * 16 + c);
    float* a = agg + (size_t)d * 64 + (c << 2);
    asm volatile("red.global.add.v4.f32 [%0], {%1,%2,%3,%4};"
                 :: "l"(a), "f"(v.x), "f"(v.y), "f"(v.z), "f"(v.w) : "memory");
    if (LAYER == 1 && c == 0) atomicAdd(&g_cnt[d], 1);
}

// ---------------- GEMM: tile 128 nodes x 64 cols (blockIdx.y = col half) ----------------
// MODE 1: h[:, half] = relu( concat(agg1*rinv, x) @ [W1l;W1r][:, half] + b1[half] )
// MODE 2: half 0 -> g_p = h @ W2l ; half 1 -> out = h @ W2r + b2
// 256 threads: cg = tid&7 (cols cg*4..+3 and 32+cg*4..+3), ng = tid>>3 (nodes ng*4..+3).
// Per thread 4n x 8c = 16 f32x2 accs. W loaded as ulonglong2 (ready f32x2 operands).
// K staged in 4 chunks of 32. Smem = 32KB W + 18KB A = 50KB -> 3 blocks/SM (24 warps).
extern __shared__ float sm[];

template <int MODE>
__global__ __launch_bounds__(256, 3)
void k_gemm(const float* __restrict__ xin, const float* __restrict__ Wa,
            const float* __restrict__ Wb, const float* __restrict__ bias,
            float* __restrict__ outr) {
    float* Ws = sm;                          // 128 k x 64 c floats
    float4* As4 = (float4*)(sm + 8192);      // 128 nodes x 9 float4 (8 k4 + pad)
    int tid = threadIdx.x;
    int nodeB = blockIdx.x * 128;
    int h = blockIdx.y;                      // column half

    // ---- stage W (2048 float4 = 32KB) ----
    #pragma unroll
    for (int m = 0; m < 8; m++) {
        int j = tid + 256 * m;
        int k = j >> 4, c4 = j & 15;
        float4 v;
        if (MODE == 1) {        // stacked rows 0-63 W1l, 64-127 W1r; cols h*64..
            v = __ldg((const float4*)(k < 64 ? Wa : Wb) + (k & 63) * 32 + h * 16 + c4);
        } else {                // half 0 = W2l, half 1 = W2r, each [128][64]
            v = __ldg((const float4*)(h ? Wb : Wa) + j);
        }
        ((float4*)Ws)[j] = v;
    }

    int cg = tid & 7;           // cols: cg*4..+3 and 32+cg*4..+3 (of this 64 half)
    int ng = tid >> 3;          // nodes ng*4..+3
    int cL = cg * 4;
    int cR = 32 + cg * 4;
    int n0 = ng * 4;

    // ---- bias / acc init ----
    float bl[4], br[4];
    #pragma unroll
    for (int q = 0; q < 4; q++) {
        if (MODE == 1) {
            bl[q] = __ldg(bias + h * 64 + cL + q);
            br[q] = __ldg(bias + h * 64 + cR + q);
        } else if (h == 1) {
            bl[q] = __ldg(bias + cL + q);
            br[q] = __ldg(bias + cR + q);
        } else { bl[q] = 0.f; br[q] = 0.f; }
    }
    unsigned long long acc[4][4];
    #pragma unroll
    for (int j = 0; j < 4; j++) {
        acc[j][0] = pk2(bl[0], bl[1]);
        acc[j][1] = pk2(bl[2], bl[3]);
        acc[j][2] = pk2(br[0], br[1]);
        acc[j][3] = pk2(br[2], br[3]);
    }

    // ---- 4 K-chunks of 32 ----
    for (int c = 0; c < 4; c++) {
        __syncthreads();        // protect As4 from previous chunk's readers
        #pragma unroll
        for (int m = 0; m < 4; m++) {
            int i = tid + 256 * m;
            int k4 = i & 7, node = i >> 3;
            int gnode = nodeB + node;
            float4 v = make_float4(0.f, 0.f, 0.f, 0.f);
            if (gnode < NND) {
                if (MODE == 1) {
                    if (c < 2) {        // k 0..63 : mean = agg1 * rinv
                        v = *((const float4*)g_agg1 + (size_t)gnode * 16 + c * 8 + k4);
                        int cn = g_cnt[gnode];
                        float ri = 1.f / (float)(cn < 1 ? 1 : cn);
                        v.x *= ri; v.y *= ri; v.z *= ri; v.w *= ri;
                        if (h == 0 && c == 0 && k4 == 0) g_rinv[gnode] = ri;
                    } else {            // k 64..127 : x
                        v = __ldg((const float4*)xin + (size_t)gnode * 16 + (c - 2) * 8 + k4);
                    }
                } else {
                    v = *((const float4*)g_h + (size_t)gnode * 32 + c * 8 + k4);
                }
            }
            As4[node * 9 + k4] = v;
        }
        __syncthreads();

        #pragma unroll
        for (int k4 = 0; k4 < 8; k4++) {
            float4 av[4];
            #pragma unroll
            for (int j = 0; j < 4; j++)
                av[j] = As4[(n0 + j) * 9 + k4];
            #pragma unroll
            for (int kk = 0; kk < 4; kk++) {
                int k = c * 32 + k4 * 4 + kk;
                ulonglong2 wA = *(const ulonglong2*)(Ws + k * 64 + cL);
                ulonglong2 wB = *(const ulonglong2*)(Ws + k * 64 + cR);
                #pragma unroll
                for (int j = 0; j < 4; j++) {
                    float a = (kk == 0) ? av[j].x : (kk == 1) ? av[j].y
                            : (kk == 2) ? av[j].z : av[j].w;
                    unsigned long long aa = pk2(a, a);
                    FMA2(acc[j][0], aa, wA.x);
                    FMA2(acc[j][1], aa, wA.y);
                    FMA2(acc[j][2], aa, wB.x);
                    FMA2(acc[j][3], aa, wB.y);
                }
            }
        }
    }

    // ---- write out ----
    #pragma unroll
    for (int j = 0; j < 4; j++) {
        int node = nodeB + n0 + j;
        if (node < NND) {
            float l0,l1,l2,l3,r0,r1,r2,r3;
            upk2(l0, l1, acc[j][0]);
            upk2(l2, l3, acc[j][1]);
            upk2(r0, r1, acc[j][2]);
            upk2(r2, r3, acc[j][3]);
            if (MODE == 1) {
                float* dp = g_h + (size_t)node * 128 + h * 64;
                *(float4*)(dp + cL) = make_float4(fmaxf(l0,0.f), fmaxf(l1,0.f),
                                                  fmaxf(l2,0.f), fmaxf(l3,0.f));
                *(float4*)(dp + cR) = make_float4(fmaxf(r0,0.f), fmaxf(r1,0.f),
                                                  fmaxf(r2,0.f), fmaxf(r3,0.f));
            } else {
                float* dst = (h ? outr : g_p) + (size_t)node * 64;
                *(float4*)(dst + cL) = make_float4(l0, l1, l2, l3);
                *(float4*)(dst + cR) = make_float4(r0, r1, r2, r3);
            }
        }
    }
}

// ---------------- finalize: out += agg2 * rinv ----------------
__global__ void k_final(float* __restrict__ out) {
    int t = blockIdx.x * 256 + threadIdx.x;     // exactly NND*16 = 1.6M threads
    int node = t >> 4;
    float ri = g_rinv[node];
    float4 a = ((const float4*)g_agg2)[t];
    float4 o = ((float4*)out)[t];
    o.x = fmaf(a.x, ri, o.x);
    o.y = fmaf(a.y, ri, o.y);
    o.z = fmaf(a.z, ri, o.z);
    o.w = fmaf(a.w, ri, o.w);
    ((float4*)out)[t] = o;
}

// ---------------- launch ----------------
extern "C" void kernel_launch(void* const* d_in, const int* in_sizes, int n_in,
                              void* d_out, int out_size) {
    const float* x   = nullptr;
    const float* b1  = nullptr;
    const float* b2  = nullptr;
    const int*   ei  = nullptr;
    const float* W[4] = {nullptr, nullptr, nullptr, nullptr};
    int wn = 0;
    for (int i = 0; i < n_in; i++) {
        int sz = in_sizes[i];
        if      (sz == NND * 64)  x  = (const float*)d_in[i];
        else if (sz == 2 * NE)    ei = (const int*)d_in[i];
        else if (sz == 128)       b1 = (const float*)d_in[i];
        else if (sz == 64)        b2 = (const float*)d_in[i];
        else if (sz == 8192 && wn < 4) W[wn++] = (const float*)d_in[i];
    }
    const float* W1l = W[0];
    const float* W1r = W[1];
    const float* W2l = W[2];
    const float* W2r = W[3];
    float* out = (float*)d_out;

    const int SMG = 32768 + 128 * 9 * 16;        // 32KB W + 18KB A = 51200 B
    cudaFuncSetAttribute(k_gemm<1>, cudaFuncAttributeMaxDynamicSharedMemorySize, SMG);
    cudaFuncSetAttribute(k_gemm<2>, cudaFuncAttributeMaxDynamicSharedMemorySize, SMG);

    dim3 gemm_grid((NND + 127) / 128, 2);        // 782 x 2

    k_init<<<25000, 256>>>(ei);                  // NND*64 threads
    k_scatter<1><<<62500, 256>>>(x);             // NE*16 threads, also counts degrees
    k_gemm<1><<<gemm_grid, 256, SMG>>>(x, W1l, W1r, b1, nullptr);
    k_gemm<2><<<gemm_grid, 256, SMG>>>(nullptr, W2l, W2r, b2, out);
    k_scatter<2><<<62500, 256>>>(nullptr);       // p -> agg2
    k_final<<<6250, 256>>>(out);                 // NND*16 threads
}

// round 11
// speedup vs baseline: 1.3499x; 1.1744x over previous
#include <cuda_runtime.h>

#define NND 100000
#define NE  1000000

// ---------------- device scratch (static, allocation-free) ----------------
__device__ float g_mean1[(size_t)NND * 64];  // layer-1 neighbor mean of x
__device__ float g_mean2[(size_t)NND * 64];  // layer-2 neighbor mean of p
__device__ float g_h   [(size_t)NND * 128];  // hidden activations
__device__ float g_p   [(size_t)NND * 64];   // h @ W2l (pre-aggregation)
__device__ int   g_cnt [NND];                // in-degree
__device__ int   g_px  [NND];                // block-local exclusive scan
__device__ int   g_bsum [512];               // per-block sums
__device__ int   g_bsumx[512];               // scanned block sums
__device__ int   g_rowptr[NND + 1];          // CSR row pointers
__device__ int   g_cur [NND];                // fill cursors
__device__ int   g_nbr [NE];                 // CSR neighbor (src) lists
__device__ int   g_src [NE];
__device__ int   g_dst [NE];

// ---------------- f32x2 helpers (sm_103a packed fp32 SIMD) ----------------
__device__ __forceinline__ unsigned long long pk2(float lo, float hi) {
    unsigned long long r;
    asm("mov.b64 %0, {%1, %2};" : "=l"(r) : "f"(lo), "f"(hi));
    return r;
}
__device__ __forceinline__ void upk2(float& lo, float& hi, unsigned long long v) {
    asm("mov.b64 {%0, %1}, %2;" : "=f"(lo), "=f"(hi) : "l"(v));
}
#define FMA2(d, a, b) \
    asm("fma.rn.f32x2 %0, %1, %2, %0;" : "+l"(d) : "l"(a), "l"(b))

// ---------------- CSR build ----------------
__global__ void k_zero() {
    int i = blockIdx.x * 256 + threadIdx.x;
    if (i < NND) g_cnt[i] = 0;
}

__global__ void k_edges(const int* __restrict__ ei) {
    int e = blockIdx.x * 256 + threadIdx.x;
    if (e < NE) {
        int s = ei[e];
        int d = ei[NE + e];
        s = (s < 0) ? 0 : (s >= NND ? NND - 1 : s);
        d = (d < 0) ? 0 : (d >= NND ? NND - 1 : d);
        g_src[e] = s;
        g_dst[e] = d;
        atomicAdd(&g_cnt[d], 1);
    }
}

// block-local exclusive scan of g_cnt (256/block) + block totals
__global__ void k_scanA() {
    __shared__ int sh[256];
    int tid = threadIdx.x;
    int i = blockIdx.x * 256 + tid;
    int v = (i < NND) ? g_cnt[i] : 0;
    sh[tid] = v;
    __syncthreads();
    int acc = v;
    #pragma unroll
    for (int o = 1; o < 256; o <<= 1) {
        int t = (tid >= o) ? sh[tid - o] : 0;
        __syncthreads();
        acc += t;
        sh[tid] = acc;
        __syncthreads();
    }
    if (i < NND) g_px[i] = acc - v;          // exclusive
    if (tid == 255) g_bsum[blockIdx.x] = acc;
}

// scan the 391 block sums (single block of 512)
__global__ void k_scanB(int nb) {
    __shared__ int sh[512];
    int tid = threadIdx.x;
    int v = (tid < nb) ? g_bsum[tid] : 0;
    sh[tid] = v;
    __syncthreads();
    int acc = v;
    #pragma unroll
    for (int o = 1; o < 512; o <<= 1) {
        int t = (tid >= o) ? sh[tid - o] : 0;
        __syncthreads();
        acc += t;
        sh[tid] = acc;
        __syncthreads();
    }
    if (tid < nb) g_bsumx[tid] = acc - v;    // exclusive
}

__global__ void k_scanC() {
    int i = blockIdx.x * 256 + threadIdx.x;
    if (i < NND) {
        int r = g_px[i] + g_bsumx[i >> 8];
        g_rowptr[i] = r;
        g_cur[i] = r;
    }
    if (i == 0) g_rowptr[NND] = NE;
}

__global__ void k_fill() {
    int e = blockIdx.x * 256 + threadIdx.x;
    if (e < NE) {
        int d = g_dst[e];
        int pos = atomicAdd(&g_cur[d], 1);
        g_nbr[pos] = g_src[e];
    }
}

// ---------------- gather: mean[node] = (1/max(deg,1)) * sum_{s in N(node)} feat[s] ----------------
template <int LAYER>
__global__ void k_gather(const float* __restrict__ xin) {
    int t = blockIdx.x * 256 + threadIdx.x;      // exactly NND*16 threads
    int node = t >> 4;
    int c = t & 15;
    const float* feat = (LAYER == 1) ? xin : g_p;
    float*       mean = (LAYER == 1) ? g_mean1 : g_mean2;
    int s0 = __ldg(&g_rowptr[node]);
    int s1 = __ldg(&g_rowptr[node + 1]);
    float4 acc = make_float4(0.f, 0.f, 0.f, 0.f);
    for (int j = s0; j < s1; j++) {
        int s = __ldg(&g_nbr[j]);
        float4 v = __ldg((const float4*)feat + (size_t)s * 16 + c);
        acc.x += v.x; acc.y += v.y; acc.z += v.z; acc.w += v.w;
    }
    int deg = s1 - s0;
    float ri = 1.f / (float)(deg < 1 ? 1 : deg);
    acc.x *= ri; acc.y *= ri; acc.z *= ri; acc.w *= ri;
    ((float4*)mean)[t] = acc;
}

// ---------------- GEMM: tile 128 nodes x 64 cols (blockIdx.y = col half) ----------------
// MODE 1: h[:, half] = relu( concat(mean1, x) @ [W1l;W1r][:, half] + b1[half] )
// MODE 2: half 0 -> g_p = h @ W2l ; half 1 -> out = h @ W2r + b2
// 256 threads: cg = tid&7 (cols cg*4..+3 and 32+cg*4..+3), ng = tid>>3 (nodes ng*4..+3).
// Per thread 4n x 8c = 16 f32x2 accs. W loaded as ulonglong2 (ready f32x2 operands).
// K staged in 4 chunks of 32. Smem = 32KB W + 18KB A = 50KB -> 3 blocks/SM (24 warps).
extern __shared__ float sm[];

template <int MODE>
__global__ __launch_bounds__(256, 3)
void k_gemm(const float* __restrict__ xin, const float* __restrict__ Wa,
            const float* __restrict__ Wb, const float* __restrict__ bias,
            float* __restrict__ outr) {
    float* Ws = sm;                          // 128 k x 64 c floats
    float4* As4 = (float4*)(sm + 8192);      // 128 nodes x 9 float4 (8 k4 + pad)
    int tid = threadIdx.x;
    int nodeB = blockIdx.x * 128;
    int h = blockIdx.y;                      // column half

    // ---- stage W (2048 float4 = 32KB) ----
    #pragma unroll
    for (int m = 0; m < 8; m++) {
        int j = tid + 256 * m;
        int k = j >> 4, c4 = j & 15;
        float4 v;
        if (MODE == 1) {        // stacked rows 0-63 W1l, 64-127 W1r; cols h*64..
            v = __ldg((const float4*)(k < 64 ? Wa : Wb) + (k & 63) * 32 + h * 16 + c4);
        } else {                // half 0 = W2l, half 1 = W2r, each [128][64]
            v = __ldg((const float4*)(h ? Wb : Wa) + j);
        }
        ((float4*)Ws)[j] = v;
    }

    int cg = tid & 7;           // cols: cg*4..+3 and 32+cg*4..+3 (of this 64 half)
    int ng = tid >> 3;          // nodes ng*4..+3
    int cL = cg * 4;
    int cR = 32 + cg * 4;
    int n0 = ng * 4;

    // ---- bias / acc init ----
    float bl[4], br[4];
    #pragma unroll
    for (int q = 0; q < 4; q++) {
        if (MODE == 1) {
            bl[q] = __ldg(bias + h * 64 + cL + q);
            br[q] = __ldg(bias + h * 64 + cR + q);
        } else if (h == 1) {
            bl[q] = __ldg(bias + cL + q);
            br[q] = __ldg(bias + cR + q);
        } else { bl[q] = 0.f; br[q] = 0.f; }
    }
    unsigned long long acc[4][4];
    #pragma unroll
    for (int j = 0; j < 4; j++) {
        acc[j][0] = pk2(bl[0], bl[1]);
        acc[j][1] = pk2(bl[2], bl[3]);
        acc[j][2] = pk2(br[0], br[1]);
        acc[j][3] = pk2(br[2], br[3]);
    }

    // ---- 4 K-chunks of 32 ----
    for (int c = 0; c < 4; c++) {
        __syncthreads();        // protect As4 from previous chunk's readers
        #pragma unroll
        for (int m = 0; m < 4; m++) {
            int i = tid + 256 * m;
            int k4 = i & 7, node = i >> 3;
            int gnode = nodeB + node;
            float4 v = make_float4(0.f, 0.f, 0.f, 0.f);
            if (gnode < NND) {
                if (MODE == 1) {
                    if (c < 2) {        // k 0..63 : pre-folded mean of x
                        v = *((const float4*)g_mean1 + (size_t)gnode * 16 + c * 8 + k4);
                    } else {            // k 64..127 : x
                        v = __ldg((const float4*)xin + (size_t)gnode * 16 + (c - 2) * 8 + k4);
                    }
                } else {
                    v = *((const float4*)g_h + (size_t)gnode * 32 + c * 8 + k4);
                }
            }
            As4[node * 9 + k4] = v;
        }
        __syncthreads();

        #pragma unroll
        for (int k4 = 0; k4 < 8; k4++) {
            float4 av[4];
            #pragma unroll
            for (int j = 0; j < 4; j++)
                av[j] = As4[(n0 + j) * 9 + k4];
            #pragma unroll
            for (int kk = 0; kk < 4; kk++) {
                int k = c * 32 + k4 * 4 + kk;
                ulonglong2 wA = *(const ulonglong2*)(Ws + k * 64 + cL);
                ulonglong2 wB = *(const ulonglong2*)(Ws + k * 64 + cR);
                #pragma unroll
                for (int j = 0; j < 4; j++) {
                    float a = (kk == 0) ? av[j].x : (kk == 1) ? av[j].y
                            : (kk == 2) ? av[j].z : av[j].w;
                    unsigned long long aa = pk2(a, a);
                    FMA2(acc[j][0], aa, wA.x);
                    FMA2(acc[j][1], aa, wA.y);
                    FMA2(acc[j][2], aa, wB.x);
                    FMA2(acc[j][3], aa, wB.y);
                }
            }
        }
    }

    // ---- write out ----
    #pragma unroll
    for (int j = 0; j < 4; j++) {
        int node = nodeB + n0 + j;
        if (node < NND) {
            float l0,l1,l2,l3,r0,r1,r2,r3;
            upk2(l0, l1, acc[j][0]);
            upk2(l2, l3, acc[j][1]);
            upk2(r0, r1, acc[j][2]);
            upk2(r2, r3, acc[j][3]);
            if (MODE == 1) {
                float* dp = g_h + (size_t)node * 128 + h * 64;
                *(float4*)(dp + cL) = make_float4(fmaxf(l0,0.f), fmaxf(l1,0.f),
                                                  fmaxf(l2,0.f), fmaxf(l3,0.f));
                *(float4*)(dp + cR) = make_float4(fmaxf(r0,0.f), fmaxf(r1,0.f),
                                                  fmaxf(r2,0.f), fmaxf(r3,0.f));
            } else {
                float* dst = (h ? outr : g_p) + (size_t)node * 64;
                *(float4*)(dst + cL) = make_float4(l0, l1, l2, l3);
                *(float4*)(dst + cR) = make_float4(r0, r1, r2, r3);
            }
        }
    }
}

// ---------------- finalize: out += mean2 ----------------
__global__ void k_final(float* __restrict__ out) {
    int t = blockIdx.x * 256 + threadIdx.x;     // exactly NND*16 threads
    float4 a = ((const float4*)g_mean2)[t];
    float4 o = ((float4*)out)[t];
    o.x += a.x; o.y += a.y; o.z += a.z; o.w += a.w;
    ((float4*)out)[t] = o;
}

// ---------------- launch ----------------
extern "C" void kernel_launch(void* const* d_in, const int* in_sizes, int n_in,
                              void* d_out, int out_size) {
    const float* x   = nullptr;
    const float* b1  = nullptr;
    const float* b2  = nullptr;
    const int*   ei  = nullptr;
    const float* W[4] = {nullptr, nullptr, nullptr, nullptr};
    int wn = 0;
    for (int i = 0; i < n_in; i++) {
        int sz = in_sizes[i];
        if      (sz == NND * 64)  x  = (const float*)d_in[i];
        else if (sz == 2 * NE)    ei = (const int*)d_in[i];
        else if (sz == 128)       b1 = (const float*)d_in[i];
        else if (sz == 64)        b2 = (const float*)d_in[i];
        else if (sz == 8192 && wn < 4) W[wn++] = (const float*)d_in[i];
    }
    const float* W1l = W[0];
    const float* W1r = W[1];
    const float* W2l = W[2];
    const float* W2r = W[3];
    float* out = (float*)d_out;

    const int SMG = 32768 + 128 * 9 * 16;        // 32KB W + 18KB A = 51200 B
    cudaFuncSetAttribute(k_gemm<1>, cudaFuncAttributeMaxDynamicSharedMemorySize, SMG);
    cudaFuncSetAttribute(k_gemm<2>, cudaFuncAttributeMaxDynamicSharedMemorySize, SMG);

    const int NB = (NND + 255) / 256;            // 391
    dim3 gemm_grid((NND + 127) / 128, 2);        // 782 x 2

    // CSR build
    k_zero <<<NB, 256>>>();
    k_edges<<<(NE + 255) / 256, 256>>>(ei);
    k_scanA<<<NB, 256>>>();
    k_scanB<<<1, 512>>>(NB);
    k_scanC<<<NB, 256>>>();
    k_fill <<<(NE + 255) / 256, 256>>>();
    // layer 1
    k_gather<1><<<6250, 256>>>(x);               // mean of x -> g_mean1
    k_gemm<1><<<gemm_grid, 256, SMG>>>(x, W1l, W1r, b1, nullptr);
    // layer 2 (GEMM commuted before aggregation)
    k_gemm<2><<<gemm_grid, 256, SMG>>>(nullptr, W2l, W2r, b2, out);
    k_gather<2><<<6250, 256>>>(nullptr);         // mean of p -> g_mean2
    k_final<<<6250, 256>>>(out);
}

// round 13
// speedup vs baseline: 1.4666x; 1.0865x over previous
#include <cuda_runtime.h>

#define NND 100000
#define NE  1000000

// ---------------- device scratch (static, allocation-free) ----------------
__device__ float g_mean1[(size_t)NND * 64];  // layer-1 neighbor mean of x
__device__ float g_h   [(size_t)NND * 128];  // hidden activations
__device__ float g_p   [(size_t)NND * 64];   // h @ W2l (pre-aggregation)
__device__ int   g_cnt [NND];                // in-degree
__device__ int   g_px  [NND];                // block-local exclusive scan
__device__ int   g_bsum [512];               // per-block sums
__device__ int   g_bsumx[512];               // scanned block sums
__device__ int   g_rowptr[NND + 1];          // CSR row pointers
__device__ int   g_cur [NND];                // fill cursors
__device__ int   g_nbr [NE];                 // CSR neighbor (src) lists

// ---------------- f32x2 helpers (sm_103a packed fp32 SIMD) ----------------
__device__ __forceinline__ unsigned long long pk2(float lo, float hi) {
    unsigned long long r;
    asm("mov.b64 %0, {%1, %2};" : "=l"(r) : "f"(lo), "f"(hi));
    return r;
}
__device__ __forceinline__ void upk2(float& lo, float& hi, unsigned long long v) {
    asm("mov.b64 {%0, %1}, %2;" : "=f"(lo), "=f"(hi) : "l"(v));
}
#define FMA2(d, a, b) \
    asm("fma.rn.f32x2 %0, %1, %2, %0;" : "+l"(d) : "l"(a), "l"(b))

__device__ __forceinline__ int clampn(int v) {
    return (v < 0) ? 0 : (v >= NND ? NND - 1 : v);
}

// ---------------- CSR build ----------------
__global__ void k_zero() {
    int i = blockIdx.x * 256 + threadIdx.x;
    if (i < NND) g_cnt[i] = 0;
}

__global__ void k_edges(const int* __restrict__ ei) {
    int e = blockIdx.x * 256 + threadIdx.x;
    if (e < NE) atomicAdd(&g_cnt[clampn(ei[NE + e])], 1);
}

// shuffle-based block scan (256 threads) of g_cnt + per-block totals
__global__ void k_scanA() {
    __shared__ int ws[8];
    int tid = threadIdx.x;
    int i = blockIdx.x * 256 + tid;
    int lane = tid & 31, w = tid >> 5;
    int v = (i < NND) ? g_cnt[i] : 0;
    int s = v;
    #pragma unroll
    for (int o = 1; o < 32; o <<= 1) {
        int t = __shfl_up_sync(0xffffffffu, s, o);
        if (lane >= o) s += t;
    }
    if (lane == 31) ws[w] = s;
    __syncthreads();
    if (w == 0) {
        int t = (lane < 8) ? ws[lane] : 0;
        #pragma unroll
        for (int o = 1; o < 8; o <<= 1) {
            int u = __shfl_up_sync(0xffffffffu, t, o);
            if (lane >= o) t += u;
        }
        if (lane < 8) ws[lane] = t;
    }
    __syncthreads();
    int incl = s + ((w > 0) ? ws[w - 1] : 0);
    if (i < NND) g_px[i] = incl - v;         // exclusive
    if (tid == 255) g_bsum[blockIdx.x] = incl;
}

// scan the block sums (single block of 512, shuffle-based)
__global__ void k_scanB(int nb) {
    __shared__ int ws[16];
    int tid = threadIdx.x;
    int lane = tid & 31, w = tid >> 5;
    int v = (tid < nb) ? g_bsum[tid] : 0;
    int s = v;
    #pragma unroll
    for (int o = 1; o < 32; o <<= 1) {
        int t = __shfl_up_sync(0xffffffffu, s, o);
        if (lane >= o) s += t;
    }
    if (lane == 31) ws[w] = s;
    __syncthreads();
    if (w == 0) {
        int t = (lane < 16) ? ws[lane] : 0;
        #pragma unroll
        for (int o = 1; o < 16; o <<= 1) {
            int u = __shfl_up_sync(0xffffffffu, t, o);
            if (lane >= o) t += u;
        }
        if (lane < 16) ws[lane] = t;
    }
    __syncthreads();
    int incl = s + ((w > 0) ? ws[w - 1] : 0);
    if (tid < nb) g_bsumx[tid] = incl - v;   // exclusive
}

__global__ void k_scanC() {
    int i = blockIdx.x * 256 + threadIdx.x;
    if (i < NND) {
        int r = g_px[i] + g_bsumx[i >> 8];
        g_rowptr[i] = r;
        g_cur[i] = r;
    }
    if (i == 0) g_rowptr[NND] = NE;
}

__global__ void k_fill(const int* __restrict__ ei) {
    int e = blockIdx.x * 256 + threadIdx.x;
    if (e < NE) {
        int d = clampn(ei[NE + e]);
        int pos = atomicAdd(&g_cur[d], 1);
        g_nbr[pos] = clampn(ei[e]);
    }
}

// ---------------- gather1: mean1[node] = mean of x over neighbors ----------------
__global__ void k_gather1(const float* __restrict__ xin) {
    int t = blockIdx.x * 256 + threadIdx.x;      // exactly NND*16 threads
    int node = t >> 4;
    int c = t & 15;
    int s0 = __ldg(&g_rowptr[node]);
    int s1 = __ldg(&g_rowptr[node + 1]);
    float4 a0 = make_float4(0.f, 0.f, 0.f, 0.f);
    float4 a1 = make_float4(0.f, 0.f, 0.f, 0.f);
    int j = s0;
    for (; j + 2 <= s1; j += 2) {
        int sA = __ldg(&g_nbr[j]);
        int sB = __ldg(&g_nbr[j + 1]);
        float4 vA = __ldg((const float4*)xin + (size_t)sA * 16 + c);
        float4 vB = __ldg((const float4*)xin + (size_t)sB * 16 + c);
        a0.x += vA.x; a0.y += vA.y; a0.z += vA.z; a0.w += vA.w;
        a1.x += vB.x; a1.y += vB.y; a1.z += vB.z; a1.w += vB.w;
    }
    if (j < s1) {
        int sA = __ldg(&g_nbr[j]);
        float4 vA = __ldg((const float4*)xin + (size_t)sA * 16 + c);
        a0.x += vA.x; a0.y += vA.y; a0.z += vA.z; a0.w += vA.w;
    }
    int deg = s1 - s0;
    float ri = 1.f / (float)(deg < 1 ? 1 : deg);
    float4 acc = make_float4((a0.x + a1.x) * ri, (a0.y + a1.y) * ri,
                             (a0.z + a1.z) * ri, (a0.w + a1.w) * ri);
    ((float4*)g_mean1)[t] = acc;
}

// ---------------- gather2 fused with finalize: out += mean of p over neighbors ----------------
__global__ void k_gather2(float* __restrict__ out) {
    int t = blockIdx.x * 256 + threadIdx.x;      // exactly NND*16 threads
    int node = t >> 4;
    int c = t & 15;
    int s0 = __ldg(&g_rowptr[node]);
    int s1 = __ldg(&g_rowptr[node + 1]);
    float4 a0 = make_float4(0.f, 0.f, 0.f, 0.f);
    float4 a1 = make_float4(0.f, 0.f, 0.f, 0.f);
    int j = s0;
    for (; j + 2 <= s1; j += 2) {
        int sA = __ldg(&g_nbr[j]);
        int sB = __ldg(&g_nbr[j + 1]);
        float4 vA = __ldg((const float4*)g_p + (size_t)sA * 16 + c);
        float4 vB = __ldg((const float4*)g_p + (size_t)sB * 16 + c);
        a0.x += vA.x; a0.y += vA.y; a0.z += vA.z; a0.w += vA.w;
        a1.x += vB.x; a1.y += vB.y; a1.z += vB.z; a1.w += vB.w;
    }
    if (j < s1) {
        int sA = __ldg(&g_nbr[j]);
        float4 vA = __ldg((const float4*)g_p + (size_t)sA * 16 + c);
        a0.x += vA.x; a0.y += vA.y; a0.z += vA.z; a0.w += vA.w;
    }
    int deg = s1 - s0;
    float ri = 1.f / (float)(deg < 1 ? 1 : deg);
    float4 o = ((const float4*)out)[t];
    o.x = fmaf(a0.x + a1.x, ri, o.x);
    o.y = fmaf(a0.y + a1.y, ri, o.y);
    o.z = fmaf(a0.z + a1.z, ri, o.z);
    o.w = fmaf(a0.w + a1.w, ri, o.w);
    ((float4*)out)[t] = o;
}

// ---------------- GEMM: tile 128 nodes x 64 cols (blockIdx.y = col half) ----------------
// MODE 1: h[:, half] = relu( concat(mean1, x) @ [W1l;W1r][:, half] + b1[half] )
// MODE 2: half 0 -> g_p = h @ W2l ; half 1 -> out = h @ W2r + b2
// 256 threads: cg = tid&7 (cols cg*4..+3 and 32+cg*4..+3), ng = tid>>3 (nodes ng*4..+3).
// Per thread 4n x 8c = 16 f32x2 accs. W loaded as ulonglong2 (ready f32x2 operands).
// K staged in 4 chunks of 32. Smem = 32KB W + 18KB A = 50KB -> 3 blocks/SM (24 warps).
extern __shared__ float sm[];

template <int MODE>
__global__ __launch_bounds__(256, 3)
void k_gemm(const float* __restrict__ xin, const float* __restrict__ Wa,
            const float* __restrict__ Wb, const float* __restrict__ bias,
            float* __restrict__ outr) {
    float* Ws = sm;                          // 128 k x 64 c floats
    float4* As4 = (float4*)(sm + 8192);      // 128 nodes x 9 float4 (8 k4 + pad)
    int tid = threadIdx.x;
    int nodeB = blockIdx.x * 128;
    int h = blockIdx.y;                      // column half

    // ---- stage W (2048 float4 = 32KB) ----
    #pragma unroll
    for (int m = 0; m < 8; m++) {
        int j = tid + 256 * m;
        int k = j >> 4, c4 = j & 15;
        float4 v;
        if (MODE == 1) {        // stacked rows 0-63 W1l, 64-127 W1r; cols h*64..
            v = __ldg((const float4*)(k < 64 ? Wa : Wb) + (k & 63) * 32 + h * 16 + c4);
        } else {                // half 0 = W2l, half 1 = W2r, each [128][64]
            v = __ldg((const float4*)(h ? Wb : Wa) + j);
        }
        ((float4*)Ws)[j] = v;
    }

    int cg = tid & 7;           // cols: cg*4..+3 and 32+cg*4..+3 (of this 64 half)
    int ng = tid >> 3;          // nodes ng*4..+3
    int cL = cg * 4;
    int cR = 32 + cg * 4;
    int n0 = ng * 4;

    // ---- bias / acc init ----
    float bl[4], br[4];
    #pragma unroll
    for (int q = 0; q < 4; q++) {
        if (MODE == 1) {
            bl[q] = __ldg(bias + h * 64 + cL + q);
            br[q] = __ldg(bias + h * 64 + cR + q);
        } else if (h == 1) {
            bl[q] = __ldg(bias + cL + q);
            br[q] = __ldg(bias + cR + q);
        } else { bl[q] = 0.f; br[q] = 0.f; }
    }
    unsigned long long acc[4][4];
    #pragma unroll
    for (int j = 0; j < 4; j++) {
        acc[j][0] = pk2(bl[0], bl[1]);
        acc[j][1] = pk2(bl[2], bl[3]);
        acc[j][2] = pk2(br[0], br[1]);
        acc[j][3] = pk2(br[2], br[3]);
    }

    // ---- 4 K-chunks of 32 ----
    for (int c = 0; c < 4; c++) {
        __syncthreads();        // protect As4 from previous chunk's readers
        #pragma unroll
        for (int m = 0; m < 4; m++) {
            int i = tid + 256 * m;
            int k4 = i & 7, node = i >> 3;
            int gnode = nodeB + node;
            float4 v = make_float4(0.f, 0.f, 0.f, 0.f);
            if (gnode < NND) {
                if (MODE == 1) {
                    if (c < 2) {        // k 0..63 : pre-folded mean of x
                        v = *((const float4*)g_mean1 + (size_t)gnode * 16 + c * 8 + k4);
                    } else {            // k 64..127 : x
                        v = __ldg((const float4*)xin + (size_t)gnode * 16 + (c - 2) * 8 + k4);
                    }
                } else {
                    v = *((const float4*)g_h + (size_t)gnode * 32 + c * 8 + k4);
                }
            }
            As4[node * 9 + k4] = v;
        }
        __syncthreads();

        #pragma unroll
        for (int k4 = 0; k4 < 8; k4++) {
            float4 av[4];
            #pragma unroll
            for (int j = 0; j < 4; j++)
                av[j] = As4[(n0 + j) * 9 + k4];
            #pragma unroll
            for (int kk = 0; kk < 4; kk++) {
                int k = c * 32 + k4 * 4 + kk;
                ulonglong2 wA = *(const ulonglong2*)(Ws + k * 64 + cL);
                ulonglong2 wB = *(const ulonglong2*)(Ws + k * 64 + cR);
                #pragma unroll
                for (int j = 0; j < 4; j++) {
                    float a = (kk == 0) ? av[j].x : (kk == 1) ? av[j].y
                            : (kk == 2) ? av[j].z : av[j].w;
                    unsigned long long aa = pk2(a, a);
                    FMA2(acc[j][0], aa, wA.x);
                    FMA2(acc[j][1], aa, wA.y);
                    FMA2(acc[j][2], aa, wB.x);
                    FMA2(acc[j][3], aa, wB.y);
                }
            }
        }
    }

    // ---- write out ----
    #pragma unroll
    for (int j = 0; j < 4; j++) {
        int node = nodeB + n0 + j;
        if (node < NND) {
            float l0,l1,l2,l3,r0,r1,r2,r3;
            upk2(l0, l1, acc[j][0]);
            upk2(l2, l3, acc[j][1]);
            upk2(r0, r1, acc[j][2]);
            upk2(r2, r3, acc[j][3]);
            if (MODE == 1) {
                float* dp = g_h + (size_t)node * 128 + h * 64;
                *(float4*)(dp + cL) = make_float4(fmaxf(l0,0.f), fmaxf(l1,0.f),
                                                  fmaxf(l2,0.f), fmaxf(l3,0.f));
                *(float4*)(dp + cR) = make_float4(fmaxf(r0,0.f), fmaxf(r1,0.f),
                                                  fmaxf(r2,0.f), fmaxf(r3,0.f));
            } else {
                float* dst = (h ? outr : g_p) + (size_t)node * 64;
                *(float4*)(dst + cL) = make_float4(l0, l1, l2, l3);
                *(float4*)(dst + cR) = make_float4(r0, r1, r2, r3);
            }
        }
    }
}

// ---------------- launch ----------------
extern "C" void kernel_launch(void* const* d_in, const int* in_sizes, int n_in,
                              void* d_out, int out_size) {
    const float* x   = nullptr;
    const float* b1  = nullptr;
    const float* b2  = nullptr;
    const int*   ei  = nullptr;
    const float* W[4] = {nullptr, nullptr, nullptr, nullptr};
    int wn = 0;
    for (int i = 0; i < n_in; i++) {
        int sz = in_sizes[i];
        if      (sz == NND * 64)  x  = (const float*)d_in[i];
        else if (sz == 2 * NE)    ei = (const int*)d_in[i];
        else if (sz == 128)       b1 = (const float*)d_in[i];
        else if (sz == 64)        b2 = (const float*)d_in[i];
        else if (sz == 8192 && wn < 4) W[wn++] = (const float*)d_in[i];
    }
    const float* W1l = W[0];
    const float* W1r = W[1];
    const float* W2l = W[2];
    const float* W2r = W[3];
    float* out = (float*)d_out;

    const int SMG = 32768 + 128 * 9 * 16;        // 32KB W + 18KB A = 51200 B
    cudaFuncSetAttribute(k_gemm<1>, cudaFuncAttributeMaxDynamicSharedMemorySize, SMG);
    cudaFuncSetAttribute(k_gemm<2>, cudaFuncAttributeMaxDynamicSharedMemorySize, SMG);

    const int NB = (NND + 255) / 256;            // 391
    dim3 gemm_grid((NND + 127) / 128, 2);        // 782 x 2

    // CSR build
    k_zero <<<NB, 256>>>();
    k_edges<<<(NE + 255) / 256, 256>>>(ei);
    k_scanA<<<NB, 256>>>();
    k_scanB<<<1, 512>>>(NB);
    k_scanC<<<NB, 256>>>();
    k_fill <<<(NE + 255) / 256, 256>>>(ei);
    // layer 1
    k_gather1<<<6250, 256>>>(x);                 // mean of x -> g_mean1
    k_gemm<1><<<gemm_grid, 256, SMG>>>(x, W1l, W1r, b1, nullptr);
    // layer 2 (GEMM commuted before aggregation; gather fused with +=)
    k_gemm<2><<<gemm_grid, 256, SMG>>>(nullptr, W2l, W2r, b2, out);
    k_gather2<<<6250, 256>>>(out);               // out += mean of p
}